// round 16
// baseline (speedup 1.0000x reference)
#include <cuda_runtime.h>

// FastECT: per-(batch,bin,theta) histogram + cumsum over bins.
// N=200000 pts (D=3), T=128 thetas, R=128 bins, B=64 batches, batch sorted.
//
// R16 = R15 hot loop (fire-and-forget red.shared u16x2 updates -- measured
// occupancy-insensitive) with per-block overhead halved again:
//  - NBLK=296 (2/SM single wave): flush+zero MIO per chip halves. u16
//    counters: per-(thread,bin) count <= 676 points/block << 65535, exact.
//  - TILE=704 >= max segment (676) -> every segment stages in ONE pass,
//    2 barriers per segment total.
// Layout: u16, 2 bins per 32-bit word per thread: word=(bin>>1)*128+t ->
// bank t%32 for any bin => update/flush/zero all conflict-free. Thread t
// owns theta t => race-free. cumsum linear => flush cumsum(partial) into
// d_out via f32 atomicAdd (exact integer adds, deterministic).

#define TT 128
#define RR 128
#define NBLK 296     // 148 SMs * 2 resident, single balanced wave
#define TILE 704     // >= max points/block (676): one stage pass/segment

typedef unsigned int       u32;
typedef unsigned char      u8;
typedef unsigned long long u64;

__device__ __forceinline__ int lower_bound_i32(const int* __restrict__ a, int n, int key) {
    int lo = 0, hi = n;
    while (lo < hi) {
        int mid = (lo + hi) >> 1;
        if (a[mid] < key) lo = mid + 1; else hi = mid;
    }
    return lo;
}

// packed f32x2 helpers (sm_103a): same per-lane rounding as scalar chain
__device__ __forceinline__ u64 pack2(float lo, float hi) {
    u64 r; asm("mov.b64 %0, {%1, %2};" : "=l"(r) : "f"(lo), "f"(hi)); return r;
}
__device__ __forceinline__ void unpack2(u64 v, float& lo, float& hi) {
    asm("mov.b64 {%0, %1}, %2;" : "=f"(lo), "=f"(hi) : "l"(v));
}
__device__ __forceinline__ u64 mul2(u64 a, u64 b) {
    u64 r; asm("mul.rn.f32x2 %0, %1, %2;" : "=l"(r) : "l"(a), "l"(b)); return r;
}
__device__ __forceinline__ u64 fma2(u64 a, u64 b, u64 c) {
    u64 r; asm("fma.rn.f32x2 %0, %1, %2, %3;" : "=l"(r) : "l"(a), "l"(b), "l"(c)); return r;
}

// bin = clip(floor(f), 0, 127) for f = 64*nh + 64 (== (nh+1)*64 exactly)
__device__ __forceinline__ u32 bin_clamp(float f) {
    return min(__float2uint_rz(f), 127u);
}

// fire-and-forget smem add (ATOMS.ADD no-return)
__device__ __forceinline__ void reds_add(u32 smem_addr, u32 val) {
    asm volatile("red.shared.add.u32 [%0], %1;" :: "r"(smem_addr), "r"(val) : "memory");
}

__global__ void __launch_bounds__(256)
k_zero(float* __restrict__ out, int n4) {
    int i = blockIdx.x * blockDim.x + threadIdx.x;
    if (i < n4) ((float4*)out)[i] = make_float4(0.f, 0.f, 0.f, 0.f);
}

__global__ void __launch_bounds__(128, 4)
k_hist(const float* __restrict__ x, const float* __restrict__ v,
       const int* __restrict__ batch, int n, float* __restrict__ out) {
    __shared__ u32 H[(RR / 2) * TT];             // u16x2: 2 bins/word/thread
    __shared__ float SX[TILE], SY[TILE], SZ[TILE];
    __shared__ int seg_end_sh;

    const int t = threadIdx.x;
    const int g = blockIdx.x;
    const u32 hbase = (u32)__cvta_generic_to_shared(H) + ((u32)t << 2);

    const int lo = (int)(((long long)g)     * n / NBLK);
    const int hi = (int)(((long long)g + 1) * n / NBLK);

    const float v0 = v[t];
    const float v1 = v[TT + t];
    const float v2 = v[2 * TT + t];
    const u64 v0p = pack2(v0, v0), v1p = pack2(v1, v1), v2p = pack2(v2, v2);
    const u64 c64p = pack2(64.0f, 64.0f);

    // zero 32KB histogram (conflict-free uint4 stores)
    {
        uint4* a = (uint4*)H;
        for (int i = t; i < (RR / 2) * TT / 4; i += 128)
            a[i] = make_uint4(0u, 0u, 0u, 0u);
    }

    int pos = lo;
    while (pos < hi) {
        if (t == 0) {
            int b = batch[pos];
            seg_end_sh = min(hi, lower_bound_i32(batch, n, b + 1));
        }
        __syncthreads();
        const int seg_end = seg_end_sh;
        const int b = batch[pos];                // uniform broadcast

        for (int base = pos; base < seg_end; base += TILE) {
            const int m = min(TILE, seg_end - base);   // == seg len (<=676)
            for (int p = t; p < m; p += 128) {
                const float* src = x + (size_t)(base + p) * 3;
                SX[p] = src[0]; SY[p] = src[1]; SZ[p] = src[2];
            }
            __syncthreads();

            int k = 0;
            for (; k + 4 <= m; k += 4) {
                // warp-uniform LDS.128 -> packed f32x2 component pairs
                ulonglong2 X = *(const ulonglong2*)(SX + k);
                ulonglong2 Y = *(const ulonglong2*)(SY + k);
                ulonglong2 Z = *(const ulonglong2*)(SZ + k);
                u64 nhA = fma2(Z.x, v2p, fma2(Y.x, v1p, mul2(X.x, v0p)));
                u64 nhB = fma2(Z.y, v2p, fma2(Y.y, v1p, mul2(X.y, v0p)));
                u64 fA  = fma2(nhA, c64p, c64p); // == (nh+1)*64 exactly
                u64 fB  = fma2(nhB, c64p, c64p);
                float f0, f1, f2, f3;
                unpack2(fA, f0, f1);
                unpack2(fB, f2, f3);
                u32 b0 = bin_clamp(f0), b1 = bin_clamp(f1);
                u32 b2 = bin_clamp(f2), b3 = bin_clamp(f3);
                // one no-return smem reduction per update (bank t%32):
                // word = (bin>>1)*128 + t, halfword = bin&1
                reds_add(hbase + ((b0 >> 1) << 9), 1u << ((b0 & 1u) << 4));
                reds_add(hbase + ((b1 >> 1) << 9), 1u << ((b1 & 1u) << 4));
                reds_add(hbase + ((b2 >> 1) << 9), 1u << ((b2 & 1u) << 4));
                reds_add(hbase + ((b3 >> 1) << 9), 1u << ((b3 & 1u) << 4));
            }
            for (; k < m; ++k) {
                float nh = fmaf(SZ[k], v2, fmaf(SY[k], v1, __fmul_rn(SX[k], v0)));
                u32 bn = bin_clamp(fmaf(nh, 64.0f, 64.0f));
                reds_add(hbase + ((bn >> 1) << 9), 1u << ((bn & 1u) << 4));
            }
            __syncthreads();                     // drains pending reductions
        }

        // flush: cumsum(partial) += out[b][bin][t]; fully unrolled.
        // LDS word (bin>>1)*128 + t (bank t%32), REDG coalesced across t.
        {
            int acc = 0;
            float* dst = out + ((size_t)b * RR) * TT + t;
#pragma unroll
            for (int bin2 = 0; bin2 < RR / 2; ++bin2) {
                u32 w = H[bin2 * 128 + t];
                H[bin2 * 128 + t] = 0u;          // rezero for next segment
                acc += (int)(w & 0xFFFFu);
                atomicAdd(dst + (bin2 * 2 + 0) * TT, (float)acc);
                acc += (int)(w >> 16);
                atomicAdd(dst + (bin2 * 2 + 1) * TT, (float)acc);
            }
        }
        pos = seg_end;
        __syncthreads();                         // protect stage/hist reuse
    }
}

extern "C" void kernel_launch(void* const* d_in, const int* in_sizes, int n_in,
                              void* d_out, int out_size) {
    const float* x     = (const float*)d_in[0];   // [200000, 3]
    const float* v     = (const float*)d_in[1];   // [3, 128]
    const int*   batch = (const int*)d_in[2];     // [200000], sorted
    const int n = in_sizes[2];

    float* out = (float*)d_out;                   // [64, 128, 128]
    const int n4 = out_size / 4;

    k_zero<<<(n4 + 255) / 256, 256>>>(out, n4);
    k_hist<<<NBLK, 128>>>(x, v, batch, n, out);
}

// round 17
// speedup vs baseline: 1.0067x; 1.0067x over previous
#include <cuda_runtime.h>

// FastECT: per-(batch,bin,theta) histogram + cumsum over bins.
// N=200000 pts (D=3), T=128 thetas, R=128 bins, B=64 batches, batch sorted.
//
// R17 = R15 (best: 592 blocks = 4/SM, u16x2 ATOMS hist) with the updates
// SPLIT across the two smem write units:
//   points 0,2 of each quad -> plain u16 RMW into HA   (LSU ld/st path)
//   points 1,3 of each quad -> red.shared u8x4 into HB (smem atomic path)
// Static arrays -> provably non-aliasing; both layouts put word index
// = f(bin)*128 + t -> bank t%32 for any bin (conflict-free).
// Safety: per-(thread,bin) counts <= 169 per path (338 pts/block) ->
// u8 bytes exact on HB, u16 on HA.
// Clean discriminating experiment: if LSU and atomic unit throughputs are
// independent, update wall halves; if shared, flat vs R15.
// cumsum linear => flush cumsum(HA+HB) into d_out via f32 atomicAdd (exact).

#define TT 128
#define RR 128
#define NBLK 592     // 148 SMs * 4 resident, single balanced wave (optimum)
#define TILE 512     // points staged per tile (SoA)

typedef unsigned int       u32;
typedef unsigned char      u8;
typedef unsigned long long u64;

__device__ __forceinline__ int lower_bound_i32(const int* __restrict__ a, int n, int key) {
    int lo = 0, hi = n;
    while (lo < hi) {
        int mid = (lo + hi) >> 1;
        if (a[mid] < key) lo = mid + 1; else hi = mid;
    }
    return lo;
}

// packed f32x2 helpers (sm_103a): same per-lane rounding as scalar chain
__device__ __forceinline__ u64 pack2(float lo, float hi) {
    u64 r; asm("mov.b64 %0, {%1, %2};" : "=l"(r) : "f"(lo), "f"(hi)); return r;
}
__device__ __forceinline__ void unpack2(u64 v, float& lo, float& hi) {
    asm("mov.b64 {%0, %1}, %2;" : "=f"(lo), "=f"(hi) : "l"(v));
}
__device__ __forceinline__ u64 mul2(u64 a, u64 b) {
    u64 r; asm("mul.rn.f32x2 %0, %1, %2;" : "=l"(r) : "l"(a), "l"(b)); return r;
}
__device__ __forceinline__ u64 fma2(u64 a, u64 b, u64 c) {
    u64 r; asm("fma.rn.f32x2 %0, %1, %2, %3;" : "=l"(r) : "l"(a), "l"(b), "l"(c)); return r;
}

// bin = clip(floor(f), 0, 127) for f = 64*nh + 64 (== (nh+1)*64 exactly)
__device__ __forceinline__ u32 bin_clamp(float f) {
    return min(__float2uint_rz(f), 127u);
}

// fire-and-forget smem add (ATOMS.ADD no-return)
__device__ __forceinline__ void reds_add(u32 smem_addr, u32 val) {
    asm volatile("red.shared.add.u32 [%0], %1;" :: "r"(smem_addr), "r"(val) : "memory");
}

__global__ void __launch_bounds__(256)
k_zero(float* __restrict__ out, int n4) {
    int i = blockIdx.x * blockDim.x + threadIdx.x;
    if (i < n4) ((float4*)out)[i] = make_float4(0.f, 0.f, 0.f, 0.f);
}

__global__ void __launch_bounds__(128, 4)
k_hist(const float* __restrict__ x, const float* __restrict__ v,
       const int* __restrict__ batch, int n, float* __restrict__ out) {
    __shared__ u32 HA[(RR / 2) * TT];            // u16x2, RMW path (pts 0,2)
    __shared__ u8  HB[RR * TT];                  // u8x4, ATOMS path (pts 1,3)
    __shared__ float SX[TILE], SY[TILE], SZ[TILE];
    __shared__ int seg_end_sh;

    const int t = threadIdx.x;
    const int g = blockIdx.x;
    u32* __restrict__ hA = HA + t;               // word index (bin>>1)*128+t
    const u32 hbaseB = (u32)__cvta_generic_to_shared(HB) + ((u32)t << 2);

    const int lo = (int)(((long long)g)     * n / NBLK);
    const int hi = (int)(((long long)g + 1) * n / NBLK);

    const float v0 = v[t];
    const float v1 = v[TT + t];
    const float v2 = v[2 * TT + t];
    const u64 v0p = pack2(v0, v0), v1p = pack2(v1, v1), v2p = pack2(v2, v2);
    const u64 c64p = pack2(64.0f, 64.0f);

    // zero both histograms (conflict-free uint4 stores)
    {
        uint4* a = (uint4*)HA;
        for (int i = t; i < (RR / 2) * TT / 4; i += 128)
            a[i] = make_uint4(0u, 0u, 0u, 0u);
        uint4* bz = (uint4*)HB;
        for (int i = t; i < (RR * TT) / 16; i += 128)
            bz[i] = make_uint4(0u, 0u, 0u, 0u);
    }

    int pos = lo;
    while (pos < hi) {
        if (t == 0) {
            int b = batch[pos];
            seg_end_sh = min(hi, lower_bound_i32(batch, n, b + 1));
        }
        __syncthreads();
        const int seg_end = seg_end_sh;
        const int b = batch[pos];                // uniform broadcast

        for (int base = pos; base < seg_end; base += TILE) {
            const int m = min(TILE, seg_end - base);
            for (int p = t; p < m; p += 128) {
                const float* src = x + (size_t)(base + p) * 3;
                SX[p] = src[0]; SY[p] = src[1]; SZ[p] = src[2];
            }
            __syncthreads();

            int k = 0;
            for (; k + 4 <= m; k += 4) {
                // warp-uniform LDS.128 -> packed f32x2 component pairs
                ulonglong2 X = *(const ulonglong2*)(SX + k);
                ulonglong2 Y = *(const ulonglong2*)(SY + k);
                ulonglong2 Z = *(const ulonglong2*)(SZ + k);
                u64 nhA = fma2(Z.x, v2p, fma2(Y.x, v1p, mul2(X.x, v0p)));
                u64 nhB = fma2(Z.y, v2p, fma2(Y.y, v1p, mul2(X.y, v0p)));
                u64 fA  = fma2(nhA, c64p, c64p); // == (nh+1)*64 exactly
                u64 fB  = fma2(nhB, c64p, c64p);
                float f0, f1, f2, f3;
                unpack2(fA, f0, f1);
                unpack2(fB, f2, f3);
                u32 b0 = bin_clamp(f0), b1 = bin_clamp(f1);
                u32 b2 = bin_clamp(f2), b3 = bin_clamp(f3);
                // pts 0,2 -> LSU RMW into HA (u16 halfwords)
                hA[(b0 >> 1) * 128] += 1u << ((b0 & 1u) << 4);
                // pts 1,3 -> atomic unit into HB (u8 bytes, no-return)
                reds_add(hbaseB + ((b1 >> 2) << 9), 1u << ((b1 & 3u) << 3));
                hA[(b2 >> 1) * 128] += 1u << ((b2 & 1u) << 4);
                reds_add(hbaseB + ((b3 >> 2) << 9), 1u << ((b3 & 3u) << 3));
            }
            for (; k < m; ++k) {
                float nh = fmaf(SZ[k], v2, fmaf(SY[k], v1, __fmul_rn(SX[k], v0)));
                u32 bn = bin_clamp(fmaf(nh, 64.0f, 64.0f));
                hA[(bn >> 1) * 128] += 1u << ((bn & 1u) << 4);
            }
            __syncthreads();                     // drains pending reductions
        }

        // flush: cumsum(HA+HB partial) += out[b][bin][t]; fully unrolled.
        // Per 4 bins: 2 HA words + 1 HB word (all bank t%32), REDG coalesced.
        {
            int acc = 0;
            u32* wb = (u32*)HB;
            float* dst = out + ((size_t)b * RR) * TT + t;
#pragma unroll
            for (int bin4 = 0; bin4 < RR / 4; ++bin4) {
                u32 a0 = HA[(2 * bin4 + 0) * 128 + t];
                u32 a1 = HA[(2 * bin4 + 1) * 128 + t];
                u32 c  = wb[bin4 * 128 + t];
                HA[(2 * bin4 + 0) * 128 + t] = 0u;   // rezero
                HA[(2 * bin4 + 1) * 128 + t] = 0u;
                wb[bin4 * 128 + t] = 0u;
                acc += (int)(a0 & 0xFFFFu) + (int)(c & 255u);
                atomicAdd(dst + (bin4 * 4 + 0) * TT, (float)acc);
                acc += (int)(a0 >> 16) + (int)((c >> 8) & 255u);
                atomicAdd(dst + (bin4 * 4 + 1) * TT, (float)acc);
                acc += (int)(a1 & 0xFFFFu) + (int)((c >> 16) & 255u);
                atomicAdd(dst + (bin4 * 4 + 2) * TT, (float)acc);
                acc += (int)(a1 >> 16) + (int)(c >> 24);
                atomicAdd(dst + (bin4 * 4 + 3) * TT, (float)acc);
            }
        }
        pos = seg_end;
        __syncthreads();                         // protect stage/hist reuse
    }
}

extern "C" void kernel_launch(void* const* d_in, const int* in_sizes, int n_in,
                              void* d_out, int out_size) {
    const float* x     = (const float*)d_in[0];   // [200000, 3]
    const float* v     = (const float*)d_in[1];   // [3, 128]
    const int*   batch = (const int*)d_in[2];     // [200000], sorted
    const int n = in_sizes[2];

    float* out = (float*)d_out;                   // [64, 128, 128]
    const int n4 = out_size / 4;

    k_zero<<<(n4 + 255) / 256, 256>>>(out, n4);
    k_hist<<<NBLK, 128>>>(x, v, batch, n, out);
}